// round 2
// baseline (speedup 1.0000x reference)
#include <cuda_runtime.h>
#include <math.h>

// Problem constants
#define NB   4
#define NS   2048
#define NHID 2048
#define NH   16
#define ND   128
#define NM   (NB*NS)                    // 8192 rows
#define OUT_ELEMS ((size_t)NB*NS*NHID)  // 16777216

// Scratch (no allocation allowed -> __device__ globals)
__device__ float g_q[(size_t)NB*NH*NS*ND];    // [B,H,S,D]  64MB
__device__ float g_ctx[(size_t)NB*NS*NHID];   // [B,S,H*D]  64MB

// ---------------------------------------------------------------------------
// Generic NT GEMM: C[m,n] = sum_k A[m,k] * W[n,k], M=8192, N=2048, K=2048.
// Tiles: BM=BN=64, BK=16, 256 threads, 4x4 per thread.
// Smem stored transposed As[k][m] / Bs[k][n] so compute reads are float4,
// conflict-free. Loader mapping keeps global reads 32B-coalesced and smem
// scatter stores at worst 2-way conflicted.
// MODE 0: plain row-major C (ld = NHID)
// MODE 1: scatter m->(b,s), n->(h,d): C[(b*NH+h)*bh_stride + s*ND + d]
// ---------------------------------------------------------------------------
template<int MODE>
__global__ __launch_bounds__(256)
void gemm_nt(const float* __restrict__ A, const float* __restrict__ W,
             float* __restrict__ C, int bh_stride)
{
    __shared__ float As[16*64];
    __shared__ float Bs[16*64];

    const int tid = threadIdx.x;
    const int tx = tid & 15, ty = tid >> 4;
    const int m0 = blockIdx.y << 6, n0 = blockIdx.x << 6;

    // loader: one float4 of A and one of W per thread per k-tile
    const int lc2 = tid & 1;
    const int ldr = (tid >> 1) & 63;
    const int lc4 = (((tid >> 7) & 1) << 1) | lc2;   // 0..3

    const float* Ag = A + (size_t)(m0 + ldr) * NHID + (lc4 << 2);
    const float* Wg = W + (size_t)(n0 + ldr) * NHID + (lc4 << 2);

    float acc[4][4];
    #pragma unroll
    for (int i = 0; i < 4; i++)
        #pragma unroll
        for (int j = 0; j < 4; j++) acc[i][j] = 0.f;

    for (int k0 = 0; k0 < NHID; k0 += 16) {
        float4 av = *(const float4*)(Ag + k0);
        float4 wv = *(const float4*)(Wg + k0);
        __syncthreads();   // previous iteration's reads complete
        As[(lc4*4+0)*64 + ldr] = av.x;
        As[(lc4*4+1)*64 + ldr] = av.y;
        As[(lc4*4+2)*64 + ldr] = av.z;
        As[(lc4*4+3)*64 + ldr] = av.w;
        Bs[(lc4*4+0)*64 + ldr] = wv.x;
        Bs[(lc4*4+1)*64 + ldr] = wv.y;
        Bs[(lc4*4+2)*64 + ldr] = wv.z;
        Bs[(lc4*4+3)*64 + ldr] = wv.w;
        __syncthreads();
        #pragma unroll
        for (int kk = 0; kk < 16; kk++) {
            float4 a = *(const float4*)&As[kk*64 + (ty << 2)];
            float4 b = *(const float4*)&Bs[kk*64 + (tx << 2)];
            float aa[4] = {a.x, a.y, a.z, a.w};
            float bb[4] = {b.x, b.y, b.z, b.w};
            #pragma unroll
            for (int i = 0; i < 4; i++)
                #pragma unroll
                for (int j = 0; j < 4; j++)
                    acc[i][j] = fmaf(aa[i], bb[j], acc[i][j]);
        }
    }

    #pragma unroll
    for (int i = 0; i < 4; i++) {
        const int m = m0 + (ty << 2) + i;
        const int n = n0 + (tx << 2);
        float4 v = make_float4(acc[i][0], acc[i][1], acc[i][2], acc[i][3]);
        if (MODE == 0) {
            *(float4*)&C[(size_t)m * NHID + n] = v;
        } else {
            const int b = m >> 11, s = m & 2047;      // m = b*NS + s
            const int h = n >> 7,  d = n & 127;       // n = h*ND + d (4 cols stay in one h)
            *(float4*)&C[(size_t)(b*NH + h) * bh_stride + (size_t)s*ND + d] = v;
        }
    }
}

// ---------------------------------------------------------------------------
// Flash attention (causal): one block per (q-tile of 64 rows, b*h).
// BM=BN=64, D=128, 256 threads.
//  - Q,K transposed in smem [128][64] (float4 conflict-free compute reads)
//  - V row-major padded [64][132]
//  - P staged through smem [64][65]
//  - online softmax with per-row m/l kept in registers, shfl row reductions
// Writes ctx in [B,S,H*D] layout for the Wo GEMM.
// ---------------------------------------------------------------------------
#define VSTR 132
#define PSTR 65
#define ATTN_SMEM ((128*64 + 128*64 + 64*VSTR + 64*PSTR) * 4)

__global__ __launch_bounds__(256)
void attn_kernel(const float* __restrict__ Q, const float* __restrict__ KV,
                 float* __restrict__ ctx)
{
    extern __shared__ float sm[];
    float* Qts = sm;                  // [128][64]
    float* Kts = Qts + 128*64;        // [128][64]
    float* Vs  = Kts + 128*64;        // [64][VSTR]
    float* Ps  = Vs  + 64*VSTR;       // [64][PSTR]

    const int qt = blockIdx.x;
    const int bh = blockIdx.y;
    const int q0 = qt << 6;
    const int tid = threadIdx.x;
    const int tx = tid & 15, ty = tid >> 4;

    const float* Qg = Q  + ((size_t)bh * NS + q0) * ND;
    const float* Kg = KV + (size_t)bh * 2 * NS * ND;
    const float* Vg = Kg + (size_t)NS * ND;

    // tile loader mapping: 2048 float4 per 64x128 tile, 8 per thread.
    const int ldc2  = tid & 1;
    const int ldr   = (tid >> 1) & 63;
    const int ldch0 = tid >> 7;   // 0/1

    // ---- load Q tile, transposed
    #pragma unroll
    for (int it = 0; it < 8; it++) {
        const int d4 = ((it*2 + ldch0) << 1) | ldc2;   // 0..31
        float4 v = *(const float4*)&Qg[(size_t)ldr * ND + (d4 << 2)];
        Qts[(d4*4+0)*64 + ldr] = v.x;
        Qts[(d4*4+1)*64 + ldr] = v.y;
        Qts[(d4*4+2)*64 + ldr] = v.z;
        Qts[(d4*4+3)*64 + ldr] = v.w;
    }

    float o[4][8];
    #pragma unroll
    for (int i = 0; i < 4; i++)
        #pragma unroll
        for (int c = 0; c < 8; c++) o[i][c] = 0.f;
    float mr[4], lsum[4];
    #pragma unroll
    for (int i = 0; i < 4; i++) { mr[i] = -1e30f; lsum[i] = 0.f; }

    const float scale = 0.08838834764831843f;   // D^-0.5

    for (int kt = 0; kt <= qt; kt++) {
        const int k0 = kt << 6;
        __syncthreads();   // all reads of previous K/V/P tiles done (incl. Q load on kt=0)
        #pragma unroll
        for (int it = 0; it < 8; it++) {
            const int d4 = ((it*2 + ldch0) << 1) | ldc2;
            float4 kv4 = *(const float4*)&Kg[(size_t)(k0 + ldr) * ND + (d4 << 2)];
            Kts[(d4*4+0)*64 + ldr] = kv4.x;
            Kts[(d4*4+1)*64 + ldr] = kv4.y;
            Kts[(d4*4+2)*64 + ldr] = kv4.z;
            Kts[(d4*4+3)*64 + ldr] = kv4.w;
            float4 vv4 = *(const float4*)&Vg[(size_t)(k0 + ldr) * ND + (d4 << 2)];
            *(float4*)&Vs[ldr*VSTR + (d4 << 2)] = vv4;
        }
        __syncthreads();

        // ---- S = Q K^T (64x64 tile, 4x4 per thread)
        float sc[4][4];
        #pragma unroll
        for (int i = 0; i < 4; i++)
            #pragma unroll
            for (int j = 0; j < 4; j++) sc[i][j] = 0.f;
        #pragma unroll 4
        for (int kk = 0; kk < 128; kk++) {
            float4 a = *(const float4*)&Qts[kk*64 + (ty << 2)];
            float4 b = *(const float4*)&Kts[kk*64 + (tx << 2)];
            float aa[4] = {a.x, a.y, a.z, a.w};
            float bb[4] = {b.x, b.y, b.z, b.w};
            #pragma unroll
            for (int i = 0; i < 4; i++)
                #pragma unroll
                for (int j = 0; j < 4; j++)
                    sc[i][j] = fmaf(aa[i], bb[j], sc[i][j]);
        }

        // scale + causal mask (only the diagonal tile is partial)
        #pragma unroll
        for (int i = 0; i < 4; i++)
            #pragma unroll
            for (int j = 0; j < 4; j++) sc[i][j] *= scale;
        if (kt == qt) {
            #pragma unroll
            for (int i = 0; i < 4; i++) {
                const int qrow = q0 + (ty << 2) + i;
                #pragma unroll
                for (int j = 0; j < 4; j++) {
                    const int kcol = k0 + (tx << 2) + j;
                    if (kcol > qrow) sc[i][j] = -1e30f;
                }
            }
        }

        // ---- online softmax, P into smem
        #pragma unroll
        for (int i = 0; i < 4; i++) {
            float rm = fmaxf(fmaxf(sc[i][0], sc[i][1]), fmaxf(sc[i][2], sc[i][3]));
            #pragma unroll
            for (int off = 8; off >= 1; off >>= 1)
                rm = fmaxf(rm, __shfl_xor_sync(0xffffffffu, rm, off));
            const float mnew = fmaxf(mr[i], rm);
            const float al = __expf(mr[i] - mnew);
            mr[i] = mnew;
            float p0 = __expf(sc[i][0] - mnew);
            float p1 = __expf(sc[i][1] - mnew);
            float p2 = __expf(sc[i][2] - mnew);
            float p3 = __expf(sc[i][3] - mnew);
            lsum[i] = lsum[i] * al + (p0 + p1 + p2 + p3);
            #pragma unroll
            for (int c = 0; c < 8; c++) o[i][c] *= al;
            const int prow = ((ty << 2) + i) * PSTR + (tx << 2);
            Ps[prow + 0] = p0;
            Ps[prow + 1] = p1;
            Ps[prow + 2] = p2;
            Ps[prow + 3] = p3;
        }
        __syncthreads();

        // ---- O += P V  (64x128 tile, 4x8 per thread: cols tx*4 and 64+tx*4)
        #pragma unroll 2
        for (int j = 0; j < 64; j++) {
            const float p0 = Ps[((ty << 2) + 0)*PSTR + j];
            const float p1 = Ps[((ty << 2) + 1)*PSTR + j];
            const float p2 = Ps[((ty << 2) + 2)*PSTR + j];
            const float p3 = Ps[((ty << 2) + 3)*PSTR + j];
            float4 v0 = *(const float4*)&Vs[j*VSTR + (tx << 2)];
            float4 v1 = *(const float4*)&Vs[j*VSTR + 64 + (tx << 2)];
            float pp[4] = {p0, p1, p2, p3};
            float vv[8] = {v0.x, v0.y, v0.z, v0.w, v1.x, v1.y, v1.z, v1.w};
            #pragma unroll
            for (int i = 0; i < 4; i++)
                #pragma unroll
                for (int c = 0; c < 8; c++)
                    o[i][c] = fmaf(pp[i], vv[c], o[i][c]);
        }
    }

    // ---- epilogue: reduce l across the 16 row-lanes, normalize, write ctx
    const int b = bh >> 4, h = bh & 15;
    #pragma unroll
    for (int i = 0; i < 4; i++) {
        float l = lsum[i];
        #pragma unroll
        for (int off = 8; off >= 1; off >>= 1)
            l += __shfl_xor_sync(0xffffffffu, l, off);
        const float inv = 1.0f / l;
        const int s = q0 + (ty << 2) + i;
        float* dst = ctx + (size_t)(b*NS + s) * NHID + h*ND;
        float4 w0 = make_float4(o[i][0]*inv, o[i][1]*inv, o[i][2]*inv, o[i][3]*inv);
        float4 w1 = make_float4(o[i][4]*inv, o[i][5]*inv, o[i][6]*inv, o[i][7]*inv);
        *(float4*)&dst[(tx << 2)]      = w0;
        *(float4*)&dst[64 + (tx << 2)] = w1;
    }
}

// ---------------------------------------------------------------------------
// d_out layout (tuple flattened): [0, 16777216) = output [B,S,HID]
//                                 [16777216, ...) = kv cache [B,H,2,S,D]
// ---------------------------------------------------------------------------
extern "C" void kernel_launch(void* const* d_in, const int* in_sizes, int n_in,
                              void* d_out, int out_size)
{
    const float* x  = (const float*)d_in[0];
    const float* Wq = (const float*)d_in[1];
    const float* Wk = (const float*)d_in[2];
    const float* Wv = (const float*)d_in[3];
    const float* Wo = (const float*)d_in[4];
    float* out = (float*)d_out;
    float* kv  = out + OUT_ELEMS;

    static float* qp   = nullptr;
    static float* ctxp = nullptr;
    if (!qp) {
        cudaGetSymbolAddress((void**)&qp,   g_q);
        cudaGetSymbolAddress((void**)&ctxp, g_ctx);
        cudaFuncSetAttribute(attn_kernel,
                             cudaFuncAttributeMaxDynamicSharedMemorySize, ATTN_SMEM);
    }

    dim3 ggrid(NHID/64, NM/64);   // (32, 128)

    // QKV projections; K/V written straight into the kv-cache region of d_out
    gemm_nt<1><<<ggrid, 256>>>(x, Wq, qp,               NS*ND);     // Q -> scratch [B,H,S,D]
    gemm_nt<1><<<ggrid, 256>>>(x, Wk, kv,               2*NS*ND);   // K -> cache slot 0
    gemm_nt<1><<<ggrid, 256>>>(x, Wv, kv + (size_t)NS*ND, 2*NS*ND); // V -> cache slot 1

    // Causal flash attention -> ctx [B,S,H*D]
    attn_kernel<<<dim3(NS/64, NB*NH), 256, ATTN_SMEM>>>(qp, kv, ctxp);

    // Output projection -> d_out[0 : B*S*HID)
    gemm_nt<0><<<ggrid, 256>>>(ctxp, Wo, out, 0);
}

// round 3
// speedup vs baseline: 2.2850x; 2.2850x over previous
#include <cuda_runtime.h>
#include <math.h>

// Problem constants
#define NB   4
#define NS   2048
#define NHID 2048
#define NH   16
#define ND   128
#define NM   (NB*NS)                    // 8192 rows
#define OUT_ELEMS ((size_t)NB*NS*NHID)  // 16777216

// Scratch (no allocation allowed -> __device__ globals)
__device__ float g_q[(size_t)NB*NH*NS*ND];    // [B,H,S,D]  64MB
__device__ float g_ctx[(size_t)NB*NS*NHID];   // [B,S,H*D]  64MB

// ---------------------------------------------------------------------------
// tf32 helpers
// ---------------------------------------------------------------------------
__device__ __forceinline__ float f2tf32(float x) {
    unsigned r;
    asm("cvt.rna.tf32.f32 %0, %1;" : "=r"(r) : "f"(x));
    return __uint_as_float(r);
}

__device__ __forceinline__ void mma_tf32(float& c0, float& c1, float& c2, float& c3,
                                         float a0, float a1, float a2, float a3,
                                         float b0, float b1)
{
    asm volatile(
        "mma.sync.aligned.m16n8k8.row.col.f32.tf32.tf32.f32 "
        "{%0,%1,%2,%3}, {%4,%5,%6,%7}, {%8,%9}, {%0,%1,%2,%3};"
        : "+f"(c0), "+f"(c1), "+f"(c2), "+f"(c3)
        : "r"(__float_as_uint(a0)), "r"(__float_as_uint(a1)),
          "r"(__float_as_uint(a2)), "r"(__float_as_uint(a3)),
          "r"(__float_as_uint(b0)), "r"(__float_as_uint(b1)));
}

// ---------------------------------------------------------------------------
// tf32 tensor-core NT GEMM: C[m,n] = sum_k A[m,k] * W[n,k]
// M=8192, N=2048, K=2048. BM=BN=128, BK=16. 256 threads = 8 warps (2 M x 4 N),
// warp tile 64x32 via m16n8k8 (4 m-tiles x 4 n-tiles). Double-buffered smem,
// pad-stride 20 (conflict-free for the fragment read pattern). tf32 conversion
// (round-to-nearest) applied once at smem-store time.
// MODE 0: row-major C (ld = NHID)
// MODE 1: scatter m->(b,s), n->(h,d): C[(b*NH+h)*bh_stride + s*ND + d]
// ---------------------------------------------------------------------------
#define GSTR 20

template<int MODE>
__global__ __launch_bounds__(256, 2)
void gemm_tf32(const float* __restrict__ A, const float* __restrict__ W,
               float* __restrict__ C, int bh_stride)
{
    __shared__ float As[2][128*GSTR];
    __shared__ float Bs[2][128*GSTR];

    const int tid  = threadIdx.x;
    const int lane = tid & 31;
    const int wid  = tid >> 5;
    const int wm   = wid & 1;          // 2 warps in M
    const int wn   = wid >> 1;         // 4 warps in N
    const int g    = lane >> 2;        // 0..7
    const int tig  = lane & 3;         // 0..3

    const int m0 = blockIdx.y << 7;
    const int n0 = blockIdx.x << 7;

    // loader: thread handles rows (tid>>2) and (tid>>2)+64, 4 floats at col (tid&3)*4
    const int lrow = tid >> 2;
    const int lc   = (tid & 3) << 2;
    const float* Ag = A + (size_t)(m0 + lrow) * NHID + lc;
    const float* Wg = W + (size_t)(n0 + lrow) * NHID + lc;

    float acc[4][4][4];
    #pragma unroll
    for (int i = 0; i < 4; i++)
        #pragma unroll
        for (int j = 0; j < 4; j++)
            #pragma unroll
            for (int r = 0; r < 4; r++) acc[i][j][r] = 0.f;

    // ---- prologue: load k-tile 0
    float4 av0 = *(const float4*)(Ag);
    float4 av1 = *(const float4*)(Ag + 64 * NHID);
    float4 wv0 = *(const float4*)(Wg);
    float4 wv1 = *(const float4*)(Wg + 64 * NHID);

    {
        float* as = As[0]; float* bs = Bs[0];
        as[lrow*GSTR + lc + 0] = f2tf32(av0.x); as[lrow*GSTR + lc + 1] = f2tf32(av0.y);
        as[lrow*GSTR + lc + 2] = f2tf32(av0.z); as[lrow*GSTR + lc + 3] = f2tf32(av0.w);
        as[(lrow+64)*GSTR + lc + 0] = f2tf32(av1.x); as[(lrow+64)*GSTR + lc + 1] = f2tf32(av1.y);
        as[(lrow+64)*GSTR + lc + 2] = f2tf32(av1.z); as[(lrow+64)*GSTR + lc + 3] = f2tf32(av1.w);
        bs[lrow*GSTR + lc + 0] = f2tf32(wv0.x); bs[lrow*GSTR + lc + 1] = f2tf32(wv0.y);
        bs[lrow*GSTR + lc + 2] = f2tf32(wv0.z); bs[lrow*GSTR + lc + 3] = f2tf32(wv0.w);
        bs[(lrow+64)*GSTR + lc + 0] = f2tf32(wv1.x); bs[(lrow+64)*GSTR + lc + 1] = f2tf32(wv1.y);
        bs[(lrow+64)*GSTR + lc + 2] = f2tf32(wv1.z); bs[(lrow+64)*GSTR + lc + 3] = f2tf32(wv1.w);
    }
    __syncthreads();

    const int arow = wm*64 + g;        // fragment base row within As
    const int brow = wn*32 + g;        // fragment base row within Bs

    int buf = 0;
    for (int k0 = 16; k0 <= NHID; k0 += 16) {
        const bool has = (k0 < NHID);
        if (has) {
            av0 = *(const float4*)(Ag + k0);
            av1 = *(const float4*)(Ag + 64 * NHID + k0);
            wv0 = *(const float4*)(Wg + k0);
            wv1 = *(const float4*)(Wg + 64 * NHID + k0);
        }

        // ---- compute current buffer
        const float* as = As[buf]; const float* bs = Bs[buf];
        #pragma unroll
        for (int ks = 0; ks < 2; ks++) {
            const int kb = ks * 8 + tig;
            float a[4][4];
            #pragma unroll
            for (int i = 0; i < 4; i++) {
                const int r = (arow + i*16) * GSTR;
                a[i][0] = as[r + kb];
                a[i][1] = as[r + 8*GSTR + kb];
                a[i][2] = as[r + kb + 4];
                a[i][3] = as[r + 8*GSTR + kb + 4];
            }
            float b[4][2];
            #pragma unroll
            for (int j = 0; j < 4; j++) {
                const int r = (brow + j*8) * GSTR;
                b[j][0] = bs[r + kb];
                b[j][1] = bs[r + kb + 4];
            }
            #pragma unroll
            for (int i = 0; i < 4; i++)
                #pragma unroll
                for (int j = 0; j < 4; j++)
                    mma_tf32(acc[i][j][0], acc[i][j][1], acc[i][j][2], acc[i][j][3],
                             a[i][0], a[i][1], a[i][2], a[i][3],
                             b[j][0], b[j][1]);
        }

        if (has) {
            float* asn = As[buf^1]; float* bsn = Bs[buf^1];
            asn[lrow*GSTR + lc + 0] = f2tf32(av0.x); asn[lrow*GSTR + lc + 1] = f2tf32(av0.y);
            asn[lrow*GSTR + lc + 2] = f2tf32(av0.z); asn[lrow*GSTR + lc + 3] = f2tf32(av0.w);
            asn[(lrow+64)*GSTR + lc + 0] = f2tf32(av1.x); asn[(lrow+64)*GSTR + lc + 1] = f2tf32(av1.y);
            asn[(lrow+64)*GSTR + lc + 2] = f2tf32(av1.z); asn[(lrow+64)*GSTR + lc + 3] = f2tf32(av1.w);
            bsn[lrow*GSTR + lc + 0] = f2tf32(wv0.x); bsn[lrow*GSTR + lc + 1] = f2tf32(wv0.y);
            bsn[lrow*GSTR + lc + 2] = f2tf32(wv0.z); bsn[lrow*GSTR + lc + 3] = f2tf32(wv0.w);
            bsn[(lrow+64)*GSTR + lc + 0] = f2tf32(wv1.x); bsn[(lrow+64)*GSTR + lc + 1] = f2tf32(wv1.y);
            bsn[(lrow+64)*GSTR + lc + 2] = f2tf32(wv1.z); bsn[(lrow+64)*GSTR + lc + 3] = f2tf32(wv1.w);
        }
        __syncthreads();
        buf ^= 1;
    }

    // ---- epilogue
    #pragma unroll
    for (int i = 0; i < 4; i++) {
        #pragma unroll
        for (int j = 0; j < 4; j++) {
            const int row0 = m0 + wm*64 + i*16 + g;
            const int col  = n0 + wn*32 + j*8 + tig*2;
            float2 v0 = make_float2(acc[i][j][0], acc[i][j][1]);
            float2 v1 = make_float2(acc[i][j][2], acc[i][j][3]);
            if (MODE == 0) {
                *(float2*)&C[(size_t)row0 * NHID + col]       = v0;
                *(float2*)&C[(size_t)(row0+8) * NHID + col]   = v1;
            } else {
                const int h = col >> 7, d = col & 127;
                {
                    const int b = row0 >> 11, s = row0 & 2047;
                    *(float2*)&C[(size_t)(b*NH + h) * bh_stride + (size_t)s*ND + d] = v0;
                }
                {
                    const int r1 = row0 + 8;
                    const int b = r1 >> 11, s = r1 & 2047;
                    *(float2*)&C[(size_t)(b*NH + h) * bh_stride + (size_t)s*ND + d] = v1;
                }
            }
        }
    }
}

// ---------------------------------------------------------------------------
// Flash attention (causal): one block per (q-tile of 64 rows, b*h).
// Unchanged from round 2 (fp32 SIMT, ~89% FFMA issue).
// ---------------------------------------------------------------------------
#define VSTR 132
#define PSTR 65
#define ATTN_SMEM ((128*64 + 128*64 + 64*VSTR + 64*PSTR) * 4)

__global__ __launch_bounds__(256)
void attn_kernel(const float* __restrict__ Q, const float* __restrict__ KV,
                 float* __restrict__ ctx)
{
    extern __shared__ float sm[];
    float* Qts = sm;                  // [128][64]
    float* Kts = Qts + 128*64;        // [128][64]
    float* Vs  = Kts + 128*64;        // [64][VSTR]
    float* Ps  = Vs  + 64*VSTR;       // [64][PSTR]

    const int qt = blockIdx.x;
    const int bh = blockIdx.y;
    const int q0 = qt << 6;
    const int tid = threadIdx.x;
    const int tx = tid & 15, ty = tid >> 4;

    const float* Qg = Q  + ((size_t)bh * NS + q0) * ND;
    const float* Kg = KV + (size_t)bh * 2 * NS * ND;
    const float* Vg = Kg + (size_t)NS * ND;

    const int ldc2  = tid & 1;
    const int ldr   = (tid >> 1) & 63;
    const int ldch0 = tid >> 7;   // 0/1

    #pragma unroll
    for (int it = 0; it < 8; it++) {
        const int d4 = ((it*2 + ldch0) << 1) | ldc2;   // 0..31
        float4 v = *(const float4*)&Qg[(size_t)ldr * ND + (d4 << 2)];
        Qts[(d4*4+0)*64 + ldr] = v.x;
        Qts[(d4*4+1)*64 + ldr] = v.y;
        Qts[(d4*4+2)*64 + ldr] = v.z;
        Qts[(d4*4+3)*64 + ldr] = v.w;
    }

    float o[4][8];
    #pragma unroll
    for (int i = 0; i < 4; i++)
        #pragma unroll
        for (int c = 0; c < 8; c++) o[i][c] = 0.f;
    float mr[4], lsum[4];
    #pragma unroll
    for (int i = 0; i < 4; i++) { mr[i] = -1e30f; lsum[i] = 0.f; }

    const float scale = 0.08838834764831843f;   // D^-0.5

    for (int kt = 0; kt <= qt; kt++) {
        const int k0 = kt << 6;
        __syncthreads();
        #pragma unroll
        for (int it = 0; it < 8; it++) {
            const int d4 = ((it*2 + ldch0) << 1) | ldc2;
            float4 kv4 = *(const float4*)&Kg[(size_t)(k0 + ldr) * ND + (d4 << 2)];
            Kts[(d4*4+0)*64 + ldr] = kv4.x;
            Kts[(d4*4+1)*64 + ldr] = kv4.y;
            Kts[(d4*4+2)*64 + ldr] = kv4.z;
            Kts[(d4*4+3)*64 + ldr] = kv4.w;
            float4 vv4 = *(const float4*)&Vg[(size_t)(k0 + ldr) * ND + (d4 << 2)];
            *(float4*)&Vs[ldr*VSTR + (d4 << 2)] = vv4;
        }
        __syncthreads();

        float sc[4][4];
        #pragma unroll
        for (int i = 0; i < 4; i++)
            #pragma unroll
            for (int j = 0; j < 4; j++) sc[i][j] = 0.f;
        #pragma unroll 4
        for (int kk = 0; kk < 128; kk++) {
            float4 a = *(const float4*)&Qts[kk*64 + (ty << 2)];
            float4 b = *(const float4*)&Kts[kk*64 + (tx << 2)];
            float aa[4] = {a.x, a.y, a.z, a.w};
            float bb[4] = {b.x, b.y, b.z, b.w};
            #pragma unroll
            for (int i = 0; i < 4; i++)
                #pragma unroll
                for (int j = 0; j < 4; j++)
                    sc[i][j] = fmaf(aa[i], bb[j], sc[i][j]);
        }

        #pragma unroll
        for (int i = 0; i < 4; i++)
            #pragma unroll
            for (int j = 0; j < 4; j++) sc[i][j] *= scale;
        if (kt == qt) {
            #pragma unroll
            for (int i = 0; i < 4; i++) {
                const int qrow = q0 + (ty << 2) + i;
                #pragma unroll
                for (int j = 0; j < 4; j++) {
                    const int kcol = k0 + (tx << 2) + j;
                    if (kcol > qrow) sc[i][j] = -1e30f;
                }
            }
        }

        #pragma unroll
        for (int i = 0; i < 4; i++) {
            float rm = fmaxf(fmaxf(sc[i][0], sc[i][1]), fmaxf(sc[i][2], sc[i][3]));
            #pragma unroll
            for (int off = 8; off >= 1; off >>= 1)
                rm = fmaxf(rm, __shfl_xor_sync(0xffffffffu, rm, off));
            const float mnew = fmaxf(mr[i], rm);
            const float al = __expf(mr[i] - mnew);
            mr[i] = mnew;
            float p0 = __expf(sc[i][0] - mnew);
            float p1 = __expf(sc[i][1] - mnew);
            float p2 = __expf(sc[i][2] - mnew);
            float p3 = __expf(sc[i][3] - mnew);
            lsum[i] = lsum[i] * al + (p0 + p1 + p2 + p3);
            #pragma unroll
            for (int c = 0; c < 8; c++) o[i][c] *= al;
            const int prow = ((ty << 2) + i) * PSTR + (tx << 2);
            Ps[prow + 0] = p0;
            Ps[prow + 1] = p1;
            Ps[prow + 2] = p2;
            Ps[prow + 3] = p3;
        }
        __syncthreads();

        #pragma unroll 2
        for (int j = 0; j < 64; j++) {
            const float p0 = Ps[((ty << 2) + 0)*PSTR + j];
            const float p1 = Ps[((ty << 2) + 1)*PSTR + j];
            const float p2 = Ps[((ty << 2) + 2)*PSTR + j];
            const float p3 = Ps[((ty << 2) + 3)*PSTR + j];
            float4 v0 = *(const float4*)&Vs[j*VSTR + (tx << 2)];
            float4 v1 = *(const float4*)&Vs[j*VSTR + 64 + (tx << 2)];
            float pp[4] = {p0, p1, p2, p3};
            float vv[8] = {v0.x, v0.y, v0.z, v0.w, v1.x, v1.y, v1.z, v1.w};
            #pragma unroll
            for (int i = 0; i < 4; i++)
                #pragma unroll
                for (int c = 0; c < 8; c++)
                    o[i][c] = fmaf(pp[i], vv[c], o[i][c]);
        }
    }

    const int b = bh >> 4, h = bh & 15;
    #pragma unroll
    for (int i = 0; i < 4; i++) {
        float l = lsum[i];
        #pragma unroll
        for (int off = 8; off >= 1; off >>= 1)
            l += __shfl_xor_sync(0xffffffffu, l, off);
        const float inv = 1.0f / l;
        const int s = q0 + (ty << 2) + i;
        float* dst = ctx + (size_t)(b*NS + s) * NHID + h*ND;
        float4 w0 = make_float4(o[i][0]*inv, o[i][1]*inv, o[i][2]*inv, o[i][3]*inv);
        float4 w1 = make_float4(o[i][4]*inv, o[i][5]*inv, o[i][6]*inv, o[i][7]*inv);
        *(float4*)&dst[(tx << 2)]      = w0;
        *(float4*)&dst[64 + (tx << 2)] = w1;
    }
}

// ---------------------------------------------------------------------------
// d_out layout (tuple flattened): [0, 16777216) = output [B,S,HID]
//                                 [16777216, ...) = kv cache [B,H,2,S,D]
// ---------------------------------------------------------------------------
extern "C" void kernel_launch(void* const* d_in, const int* in_sizes, int n_in,
                              void* d_out, int out_size)
{
    const float* x  = (const float*)d_in[0];
    const float* Wq = (const float*)d_in[1];
    const float* Wk = (const float*)d_in[2];
    const float* Wv = (const float*)d_in[3];
    const float* Wo = (const float*)d_in[4];
    float* out = (float*)d_out;
    float* kv  = out + OUT_ELEMS;

    static float* qp   = nullptr;
    static float* ctxp = nullptr;
    if (!qp) {
        cudaGetSymbolAddress((void**)&qp,   g_q);
        cudaGetSymbolAddress((void**)&ctxp, g_ctx);
        cudaFuncSetAttribute(attn_kernel,
                             cudaFuncAttributeMaxDynamicSharedMemorySize, ATTN_SMEM);
    }

    dim3 ggrid(NHID/128, NM/128);   // (16, 64)

    // QKV projections; K/V written straight into the kv-cache region of d_out
    gemm_tf32<1><<<ggrid, 256>>>(x, Wq, qp,                 NS*ND);     // Q -> [B,H,S,D]
    gemm_tf32<1><<<ggrid, 256>>>(x, Wk, kv,                 2*NS*ND);   // K -> cache slot 0
    gemm_tf32<1><<<ggrid, 256>>>(x, Wv, kv + (size_t)NS*ND, 2*NS*ND);   // V -> cache slot 1

    // Causal flash attention -> ctx [B,S,H*D]
    attn_kernel<<<dim3(NS/64, NB*NH), 256, ATTN_SMEM>>>(qp, kv, ctxp);

    // Output projection -> d_out[0 : B*S*HID)
    gemm_tf32<0><<<ggrid, 256>>>(ctxp, Wo, out, 0);
}

// round 6
// speedup vs baseline: 3.3176x; 1.4519x over previous
#include <cuda_runtime.h>
#include <math.h>

// Problem constants
#define NB   4
#define NS   2048
#define NHID 2048
#define NH   16
#define ND   128
#define NM   (NB*NS)                    // 8192 rows
#define OUT_ELEMS ((size_t)NB*NS*NHID)  // 16777216

// Scratch (no allocation allowed -> __device__ globals)
__device__ float g_q[(size_t)NB*NH*NS*ND];    // [B,H,S,D]  64MB
__device__ float g_ctx[(size_t)NB*NS*NHID];   // [B,S,H*D]  64MB

// ---------------------------------------------------------------------------
// tf32 helpers
// ---------------------------------------------------------------------------
__device__ __forceinline__ float f2tf32(float x) {
    unsigned r;
    asm("cvt.rna.tf32.f32 %0, %1;" : "=r"(r) : "f"(x));
    return __uint_as_float(r);
}

__device__ __forceinline__ void mma_tf32(float& c0, float& c1, float& c2, float& c3,
                                         float a0, float a1, float a2, float a3,
                                         float b0, float b1)
{
    asm volatile(
        "mma.sync.aligned.m16n8k8.row.col.f32.tf32.tf32.f32 "
        "{%0,%1,%2,%3}, {%4,%5,%6,%7}, {%8,%9}, {%0,%1,%2,%3};"
        : "+f"(c0), "+f"(c1), "+f"(c2), "+f"(c3)
        : "r"(__float_as_uint(a0)), "r"(__float_as_uint(a1)),
          "r"(__float_as_uint(a2)), "r"(__float_as_uint(a3)),
          "r"(__float_as_uint(b0)), "r"(__float_as_uint(b1)));
}

// ---------------------------------------------------------------------------
// tf32 tensor-core NT GEMM (unchanged from round 3, known-good)
// ---------------------------------------------------------------------------
#define GSTR 20

template<int MODE>
__global__ __launch_bounds__(256, 2)
void gemm_tf32(const float* __restrict__ A, const float* __restrict__ W,
               float* __restrict__ C, int bh_stride)
{
    __shared__ float As[2][128*GSTR];
    __shared__ float Bs[2][128*GSTR];

    const int tid  = threadIdx.x;
    const int lane = tid & 31;
    const int wid  = tid >> 5;
    const int wm   = wid & 1;
    const int wn   = wid >> 1;
    const int g    = lane >> 2;
    const int tig  = lane & 3;

    const int m0 = blockIdx.y << 7;
    const int n0 = blockIdx.x << 7;

    const int lrow = tid >> 2;
    const int lc   = (tid & 3) << 2;
    const float* Ag = A + (size_t)(m0 + lrow) * NHID + lc;
    const float* Wg = W + (size_t)(n0 + lrow) * NHID + lc;

    float acc[4][4][4];
    #pragma unroll
    for (int i = 0; i < 4; i++)
        #pragma unroll
        for (int j = 0; j < 4; j++)
            #pragma unroll
            for (int r = 0; r < 4; r++) acc[i][j][r] = 0.f;

    float4 av0 = *(const float4*)(Ag);
    float4 av1 = *(const float4*)(Ag + 64 * NHID);
    float4 wv0 = *(const float4*)(Wg);
    float4 wv1 = *(const float4*)(Wg + 64 * NHID);

    {
        float* as = As[0]; float* bs = Bs[0];
        as[lrow*GSTR + lc + 0] = f2tf32(av0.x); as[lrow*GSTR + lc + 1] = f2tf32(av0.y);
        as[lrow*GSTR + lc + 2] = f2tf32(av0.z); as[lrow*GSTR + lc + 3] = f2tf32(av0.w);
        as[(lrow+64)*GSTR + lc + 0] = f2tf32(av1.x); as[(lrow+64)*GSTR + lc + 1] = f2tf32(av1.y);
        as[(lrow+64)*GSTR + lc + 2] = f2tf32(av1.z); as[(lrow+64)*GSTR + lc + 3] = f2tf32(av1.w);
        bs[lrow*GSTR + lc + 0] = f2tf32(wv0.x); bs[lrow*GSTR + lc + 1] = f2tf32(wv0.y);
        bs[lrow*GSTR + lc + 2] = f2tf32(wv0.z); bs[lrow*GSTR + lc + 3] = f2tf32(wv0.w);
        bs[(lrow+64)*GSTR + lc + 0] = f2tf32(wv1.x); bs[(lrow+64)*GSTR + lc + 1] = f2tf32(wv1.y);
        bs[(lrow+64)*GSTR + lc + 2] = f2tf32(wv1.z); bs[(lrow+64)*GSTR + lc + 3] = f2tf32(wv1.w);
    }
    __syncthreads();

    const int arow = wm*64 + g;
    const int brow = wn*32 + g;

    int buf = 0;
    for (int k0 = 16; k0 <= NHID; k0 += 16) {
        const bool has = (k0 < NHID);
        if (has) {
            av0 = *(const float4*)(Ag + k0);
            av1 = *(const float4*)(Ag + 64 * NHID + k0);
            wv0 = *(const float4*)(Wg + k0);
            wv1 = *(const float4*)(Wg + 64 * NHID + k0);
        }

        const float* as = As[buf]; const float* bs = Bs[buf];
        #pragma unroll
        for (int ks = 0; ks < 2; ks++) {
            const int kb = ks * 8 + tig;
            float a[4][4];
            #pragma unroll
            for (int i = 0; i < 4; i++) {
                const int r = (arow + i*16) * GSTR;
                a[i][0] = as[r + kb];
                a[i][1] = as[r + 8*GSTR + kb];
                a[i][2] = as[r + kb + 4];
                a[i][3] = as[r + 8*GSTR + kb + 4];
            }
            float b[4][2];
            #pragma unroll
            for (int j = 0; j < 4; j++) {
                const int r = (brow + j*8) * GSTR;
                b[j][0] = bs[r + kb];
                b[j][1] = bs[r + kb + 4];
            }
            #pragma unroll
            for (int i = 0; i < 4; i++)
                #pragma unroll
                for (int j = 0; j < 4; j++)
                    mma_tf32(acc[i][j][0], acc[i][j][1], acc[i][j][2], acc[i][j][3],
                             a[i][0], a[i][1], a[i][2], a[i][3],
                             b[j][0], b[j][1]);
        }

        if (has) {
            float* asn = As[buf^1]; float* bsn = Bs[buf^1];
            asn[lrow*GSTR + lc + 0] = f2tf32(av0.x); asn[lrow*GSTR + lc + 1] = f2tf32(av0.y);
            asn[lrow*GSTR + lc + 2] = f2tf32(av0.z); asn[lrow*GSTR + lc + 3] = f2tf32(av0.w);
            asn[(lrow+64)*GSTR + lc + 0] = f2tf32(av1.x); asn[(lrow+64)*GSTR + lc + 1] = f2tf32(av1.y);
            asn[(lrow+64)*GSTR + lc + 2] = f2tf32(av1.z); asn[(lrow+64)*GSTR + lc + 3] = f2tf32(av1.w);
            bsn[lrow*GSTR + lc + 0] = f2tf32(wv0.x); bsn[lrow*GSTR + lc + 1] = f2tf32(wv0.y);
            bsn[lrow*GSTR + lc + 2] = f2tf32(wv0.z); bsn[lrow*GSTR + lc + 3] = f2tf32(wv0.w);
            bsn[(lrow+64)*GSTR + lc + 0] = f2tf32(wv1.x); bsn[(lrow+64)*GSTR + lc + 1] = f2tf32(wv1.y);
            bsn[(lrow+64)*GSTR + lc + 2] = f2tf32(wv1.z); bsn[(lrow+64)*GSTR + lc + 3] = f2tf32(wv1.w);
        }
        __syncthreads();
        buf ^= 1;
    }

    #pragma unroll
    for (int i = 0; i < 4; i++) {
        #pragma unroll
        for (int j = 0; j < 4; j++) {
            const int row0 = m0 + wm*64 + i*16 + g;
            const int col  = n0 + wn*32 + j*8 + tig*2;
            float2 v0 = make_float2(acc[i][j][0], acc[i][j][1]);
            float2 v1 = make_float2(acc[i][j][2], acc[i][j][3]);
            if (MODE == 0) {
                *(float2*)&C[(size_t)row0 * NHID + col]       = v0;
                *(float2*)&C[(size_t)(row0+8) * NHID + col]   = v1;
            } else {
                const int h = col >> 7, d = col & 127;
                {
                    const int b = row0 >> 11, s = row0 & 2047;
                    *(float2*)&C[(size_t)(b*NH + h) * bh_stride + (size_t)s*ND + d] = v0;
                }
                {
                    const int r1 = row0 + 8;
                    const int b = r1 >> 11, s = r1 & 2047;
                    *(float2*)&C[(size_t)(b*NH + h) * bh_stride + (size_t)s*ND + d] = v1;
                }
            }
        }
    }
}

// ---------------------------------------------------------------------------
// Tensor-core flash attention (causal), tf32 mma for QK^T and PV.
// One block per (64-row q-tile, b*h). 256 threads = 8 warps (2 M x 4 N).
// S warp tile 32x16 (2x2 m16n8k8), O warp tile 32x32 (2x4 m16n8k8).
// Q/K row-major smem stride 132, V transposed [d][s] stride 68, P stride 68.
// All strides ≡ 4 (mod 32) -> fragment scalar LDS are bank-conflict-free.
// Online softmax in fp32; P rounded to tf32 BEFORE entering l (consistency).
// ---------------------------------------------------------------------------
#define QSTR 132
#define TVSTR 68
#define TPSTR 68
#define ATTN_SMEM ((64*QSTR + 64*QSTR + 128*TVSTR + 64*TPSTR + 256 + 256) * 4)

__global__ __launch_bounds__(256)
void attn_tc(const float* __restrict__ Q, const float* __restrict__ KV,
             float* __restrict__ ctx)
{
    extern __shared__ float sm[];
    float* Qs   = sm;                    // [64][QSTR]
    float* Ks   = Qs + 64*QSTR;          // [64][QSTR]
    float* Vs   = Ks + 64*QSTR;          // [128][TVSTR]  (transposed: [d][s])
    float* Ps   = Vs + 128*TVSTR;        // [64][TPSTR]
    float* rmax = Ps + 64*TPSTR;         // [4][64]
    float* rsum = rmax + 256;            // [4][64]

    const int qt = gridDim.x - 1 - blockIdx.x;   // longest blocks first
    const int bh = blockIdx.y;
    const int q0 = qt << 6;
    const int tid  = threadIdx.x;
    const int lane = tid & 31;
    const int wid  = tid >> 5;
    const int wm   = wid & 1;     // 2 warps in M (q rows)
    const int wn   = wid >> 1;    // 4 warps in N
    const int g    = lane >> 2;   // 0..7
    const int tig  = lane & 3;    // 0..3

    const float* Qg = Q  + ((size_t)bh * NS + q0) * ND;
    const float* Kg = KV + (size_t)bh * 2 * NS * ND;
    const float* Vg = Kg + (size_t)NS * ND;

    // tile loader: 64x128 floats, 256 threads, 8 float4 each
    const int ldc2  = tid & 1;
    const int ldr   = (tid >> 1) & 63;
    const int ldch0 = tid >> 7;

    // ---- load Q tile (row-major, tf32)
    #pragma unroll
    for (int it = 0; it < 8; it++) {
        const int d4 = ((it*2 + ldch0) << 1) | ldc2;   // 0..31
        float4 v = *(const float4*)&Qg[(size_t)ldr * ND + (d4 << 2)];
        float4 t = make_float4(f2tf32(v.x), f2tf32(v.y), f2tf32(v.z), f2tf32(v.w));
        *(float4*)&Qs[ldr*QSTR + (d4 << 2)] = t;
    }

    float o_acc[2][4][4];
    #pragma unroll
    for (int i = 0; i < 2; i++)
        #pragma unroll
        for (int j = 0; j < 4; j++)
            #pragma unroll
            for (int r = 0; r < 4; r++) o_acc[i][j][r] = 0.f;
    float m_st[2][2], l_st[2][2];
    #pragma unroll
    for (int i = 0; i < 2; i++)
        #pragma unroll
        for (int h = 0; h < 2; h++) { m_st[i][h] = -1e30f; l_st[i][h] = 0.f; }

    const float scale = 0.08838834764831843f;

    for (int kt = 0; kt <= qt; kt++) {
        const int k0 = kt << 6;
        __syncthreads();   // previous tile fully consumed
        #pragma unroll
        for (int it = 0; it < 8; it++) {
            const int d4 = ((it*2 + ldch0) << 1) | ldc2;
            float4 kv4 = *(const float4*)&Kg[(size_t)(k0 + ldr) * ND + (d4 << 2)];
            float4 kt4 = make_float4(f2tf32(kv4.x), f2tf32(kv4.y), f2tf32(kv4.z), f2tf32(kv4.w));
            *(float4*)&Ks[ldr*QSTR + (d4 << 2)] = kt4;
            float4 vv4 = *(const float4*)&Vg[(size_t)(k0 + ldr) * ND + (d4 << 2)];
            Vs[(d4*4+0)*TVSTR + ldr] = f2tf32(vv4.x);
            Vs[(d4*4+1)*TVSTR + ldr] = f2tf32(vv4.y);
            Vs[(d4*4+2)*TVSTR + ldr] = f2tf32(vv4.z);
            Vs[(d4*4+3)*TVSTR + ldr] = f2tf32(vv4.w);
        }
        __syncthreads();

        // ---- S = Q K^T : warp tile 32x16, k=128
        float s_acc[2][2][4];
        #pragma unroll
        for (int i = 0; i < 2; i++)
            #pragma unroll
            for (int j = 0; j < 2; j++)
                #pragma unroll
                for (int r = 0; r < 4; r++) s_acc[i][j][r] = 0.f;

        #pragma unroll
        for (int ks = 0; ks < 16; ks++) {
            const int kb = ks*8 + tig;
            float a[2][4];
            #pragma unroll
            for (int i = 0; i < 2; i++) {
                const int r = (wm*32 + i*16 + g) * QSTR;
                a[i][0] = Qs[r + kb];
                a[i][1] = Qs[r + 8*QSTR + kb];
                a[i][2] = Qs[r + kb + 4];
                a[i][3] = Qs[r + 8*QSTR + kb + 4];
            }
            float b[2][2];
            #pragma unroll
            for (int j = 0; j < 2; j++) {
                const int r = (wn*16 + j*8 + g) * QSTR;
                b[j][0] = Ks[r + kb];
                b[j][1] = Ks[r + kb + 4];
            }
            #pragma unroll
            for (int i = 0; i < 2; i++)
                #pragma unroll
                for (int j = 0; j < 2; j++)
                    mma_tf32(s_acc[i][j][0], s_acc[i][j][1], s_acc[i][j][2], s_acc[i][j][3],
                             a[i][0], a[i][1], a[i][2], a[i][3],
                             b[j][0], b[j][1]);
        }

        // scale + causal mask (diag tile only)
        #pragma unroll
        for (int i = 0; i < 2; i++)
            #pragma unroll
            for (int j = 0; j < 2; j++)
                #pragma unroll
                for (int r = 0; r < 4; r++) s_acc[i][j][r] *= scale;
        if (kt == qt) {
            #pragma unroll
            for (int i = 0; i < 2; i++)
                #pragma unroll
                for (int j = 0; j < 2; j++)
                    #pragma unroll
                    for (int r = 0; r < 4; r++) {
                        const int row = q0 + wm*32 + i*16 + g + ((r >> 1) << 3);
                        const int col = k0 + wn*16 + j*8 + tig*2 + (r & 1);
                        if (col > row) s_acc[i][j][r] = -1e30f;
                    }
        }

        // ---- phase A: per-warp row max partials
        #pragma unroll
        for (int i = 0; i < 2; i++)
            #pragma unroll
            for (int h = 0; h < 2; h++) {
                float mx = fmaxf(fmaxf(s_acc[i][0][h*2], s_acc[i][0][h*2+1]),
                                 fmaxf(s_acc[i][1][h*2], s_acc[i][1][h*2+1]));
                mx = fmaxf(mx, __shfl_xor_sync(0xffffffffu, mx, 1));
                mx = fmaxf(mx, __shfl_xor_sync(0xffffffffu, mx, 2));
                if (tig == 0) rmax[wn*64 + wm*32 + i*16 + h*8 + g] = mx;
            }
        __syncthreads();

        // ---- phase B: final max, exp, P -> smem, partial sums, rescale O
        float al[2][2];
        #pragma unroll
        for (int i = 0; i < 2; i++)
            #pragma unroll
            for (int h = 0; h < 2; h++) {
                const int row = wm*32 + i*16 + h*8 + g;
                float rm = fmaxf(fmaxf(rmax[row], rmax[64+row]),
                                 fmaxf(rmax[128+row], rmax[192+row]));
                const float mnew = fmaxf(m_st[i][h], rm);
                al[i][h] = __expf(m_st[i][h] - mnew);
                m_st[i][h] = mnew;
                float psum = 0.f;
                #pragma unroll
                for (int j = 0; j < 2; j++) {
                    float p0 = f2tf32(__expf(s_acc[i][j][h*2]   - mnew));
                    float p1 = f2tf32(__expf(s_acc[i][j][h*2+1] - mnew));
                    psum += p0 + p1;
                    *(float2*)&Ps[row*TPSTR + wn*16 + j*8 + tig*2] = make_float2(p0, p1);
                }
                psum += __shfl_xor_sync(0xffffffffu, psum, 1);
                psum += __shfl_xor_sync(0xffffffffu, psum, 2);
                if (tig == 0) rsum[wn*64 + row] = psum;
                #pragma unroll
                for (int j = 0; j < 4; j++) {
                    o_acc[i][j][h*2]   *= al[i][h];
                    o_acc[i][j][h*2+1] *= al[i][h];
                }
            }
        __syncthreads();

        // ---- phase C: combine row sums
        #pragma unroll
        for (int i = 0; i < 2; i++)
            #pragma unroll
            for (int h = 0; h < 2; h++) {
                const int row = wm*32 + i*16 + h*8 + g;
                const float tot = (rsum[row] + rsum[64+row]) + (rsum[128+row] + rsum[192+row]);
                l_st[i][h] = l_st[i][h] * al[i][h] + tot;
            }

        // ---- O += P V : warp tile 32x32, k=64
        #pragma unroll
        for (int ks = 0; ks < 8; ks++) {
            const int kb = ks*8 + tig;
            float a[2][4];
            #pragma unroll
            for (int i = 0; i < 2; i++) {
                const int r = (wm*32 + i*16 + g) * TPSTR;
                a[i][0] = Ps[r + kb];
                a[i][1] = Ps[r + 8*TPSTR + kb];
                a[i][2] = Ps[r + kb + 4];
                a[i][3] = Ps[r + 8*TPSTR + kb + 4];
            }
            float b[4][2];
            #pragma unroll
            for (int j = 0; j < 4; j++) {
                const int r = (wn*32 + j*8 + g) * TVSTR;
                b[j][0] = Vs[r + kb];
                b[j][1] = Vs[r + kb + 4];
            }
            #pragma unroll
            for (int i = 0; i < 2; i++)
                #pragma unroll
                for (int j = 0; j < 4; j++)
                    mma_tf32(o_acc[i][j][0], o_acc[i][j][1], o_acc[i][j][2], o_acc[i][j][3],
                             a[i][0], a[i][1], a[i][2], a[i][3],
                             b[j][0], b[j][1]);
        }
    }

    // ---- epilogue: normalize, write ctx [B,S,H*D]
    const int b = bh >> 4, hh = bh & 15;
    #pragma unroll
    for (int i = 0; i < 2; i++)
        #pragma unroll
        for (int h = 0; h < 2; h++) {
            const int row = wm*32 + i*16 + h*8 + g;
            const int s = q0 + row;
            const float inv = 1.0f / l_st[i][h];
            float* dst = ctx + (size_t)(b*NS + s) * NHID + hh*ND;
            #pragma unroll
            for (int j = 0; j < 4; j++) {
                const int col = wn*32 + j*8 + tig*2;
                *(float2*)&dst[col] =
                    make_float2(o_acc[i][j][h*2] * inv, o_acc[i][j][h*2+1] * inv);
            }
        }
}

// ---------------------------------------------------------------------------
// d_out layout (tuple flattened): [0, 16777216) = output [B,S,HID]
//                                 [16777216, ...) = kv cache [B,H,2,S,D]
// ---------------------------------------------------------------------------
extern "C" void kernel_launch(void* const* d_in, const int* in_sizes, int n_in,
                              void* d_out, int out_size)
{
    const float* x  = (const float*)d_in[0];
    const float* Wq = (const float*)d_in[1];
    const float* Wk = (const float*)d_in[2];
    const float* Wv = (const float*)d_in[3];
    const float* Wo = (const float*)d_in[4];
    float* out = (float*)d_out;
    float* kv  = out + OUT_ELEMS;

    static float* qp   = nullptr;
    static float* ctxp = nullptr;
    if (!qp) {
        cudaGetSymbolAddress((void**)&qp,   g_q);
        cudaGetSymbolAddress((void**)&ctxp, g_ctx);
        cudaFuncSetAttribute(attn_tc,
                             cudaFuncAttributeMaxDynamicSharedMemorySize, ATTN_SMEM);
    }

    dim3 ggrid(NHID/128, NM/128);   // (16, 64)

    gemm_tf32<1><<<ggrid, 256>>>(x, Wq, qp,                 NS*ND);     // Q -> [B,H,S,D]
    gemm_tf32<1><<<ggrid, 256>>>(x, Wk, kv,                 2*NS*ND);   // K -> cache slot 0
    gemm_tf32<1><<<ggrid, 256>>>(x, Wv, kv + (size_t)NS*ND, 2*NS*ND);   // V -> cache slot 1

    attn_tc<<<dim3(NS/64, NB*NH), 256, ATTN_SMEM>>>(qp, kv, ctxp);

    gemm_tf32<0><<<ggrid, 256>>>(ctxp, Wo, out, 0);
}

// round 8
// speedup vs baseline: 3.5024x; 1.0557x over previous
#include <cuda_runtime.h>
#include <math.h>
#include <stdint.h>

// Problem constants
#define NB   4
#define NS   2048
#define NHID 2048
#define NH   16
#define ND   128
#define NM   (NB*NS)                    // 8192 rows
#define OUT_ELEMS ((size_t)NB*NS*NHID)  // 16777216

// Scratch (no allocation allowed -> __device__ globals)
__device__ float g_q[(size_t)NB*NH*NS*ND];    // [B,H,S,D]  64MB
__device__ float g_ctx[(size_t)NB*NS*NHID];   // [B,S,H*D]  64MB

// ---------------------------------------------------------------------------
// helpers
// ---------------------------------------------------------------------------
__device__ __forceinline__ float f2tf32(float x) {
    unsigned r;
    asm("cvt.rna.tf32.f32 %0, %1;" : "=r"(r) : "f"(x));
    return __uint_as_float(r);
}

__device__ __forceinline__ void mma_tf32(float& c0, float& c1, float& c2, float& c3,
                                         float a0, float a1, float a2, float a3,
                                         float b0, float b1)
{
    asm volatile(
        "mma.sync.aligned.m16n8k8.row.col.f32.tf32.tf32.f32 "
        "{%0,%1,%2,%3}, {%4,%5,%6,%7}, {%8,%9}, {%0,%1,%2,%3};"
        : "+f"(c0), "+f"(c1), "+f"(c2), "+f"(c3)
        : "r"(__float_as_uint(a0)), "r"(__float_as_uint(a1)),
          "r"(__float_as_uint(a2)), "r"(__float_as_uint(a3)),
          "r"(__float_as_uint(b0)), "r"(__float_as_uint(b1)));
}

__device__ __forceinline__ uint32_t smem_u32(const void* p) {
    uint32_t a;
    asm("{ .reg .u64 t; cvta.to.shared.u64 t, %1; cvt.u32.u64 %0, t; }" : "=r"(a) : "l"(p));
    return a;
}

// ---------------------------------------------------------------------------
// tf32 tensor-core NT GEMM (unchanged from round 3/6, known-good, ~89% of
// legacy-HMMA tf32 peak)
// ---------------------------------------------------------------------------
#define GSTR 20

template<int MODE>
__global__ __launch_bounds__(256, 2)
void gemm_tf32(const float* __restrict__ A, const float* __restrict__ W,
               float* __restrict__ C, int bh_stride)
{
    __shared__ float As[2][128*GSTR];
    __shared__ float Bs[2][128*GSTR];

    const int tid  = threadIdx.x;
    const int lane = tid & 31;
    const int wid  = tid >> 5;
    const int wm   = wid & 1;
    const int wn   = wid >> 1;
    const int g    = lane >> 2;
    const int tig  = lane & 3;

    const int m0 = blockIdx.y << 7;
    const int n0 = blockIdx.x << 7;

    const int lrow = tid >> 2;
    const int lc   = (tid & 3) << 2;
    const float* Ag = A + (size_t)(m0 + lrow) * NHID + lc;
    const float* Wg = W + (size_t)(n0 + lrow) * NHID + lc;

    float acc[4][4][4];
    #pragma unroll
    for (int i = 0; i < 4; i++)
        #pragma unroll
        for (int j = 0; j < 4; j++)
            #pragma unroll
            for (int r = 0; r < 4; r++) acc[i][j][r] = 0.f;

    float4 av0 = *(const float4*)(Ag);
    float4 av1 = *(const float4*)(Ag + 64 * NHID);
    float4 wv0 = *(const float4*)(Wg);
    float4 wv1 = *(const float4*)(Wg + 64 * NHID);

    {
        float* as = As[0]; float* bs = Bs[0];
        as[lrow*GSTR + lc + 0] = f2tf32(av0.x); as[lrow*GSTR + lc + 1] = f2tf32(av0.y);
        as[lrow*GSTR + lc + 2] = f2tf32(av0.z); as[lrow*GSTR + lc + 3] = f2tf32(av0.w);
        as[(lrow+64)*GSTR + lc + 0] = f2tf32(av1.x); as[(lrow+64)*GSTR + lc + 1] = f2tf32(av1.y);
        as[(lrow+64)*GSTR + lc + 2] = f2tf32(av1.z); as[(lrow+64)*GSTR + lc + 3] = f2tf32(av1.w);
        bs[lrow*GSTR + lc + 0] = f2tf32(wv0.x); bs[lrow*GSTR + lc + 1] = f2tf32(wv0.y);
        bs[lrow*GSTR + lc + 2] = f2tf32(wv0.z); bs[lrow*GSTR + lc + 3] = f2tf32(wv0.w);
        bs[(lrow+64)*GSTR + lc + 0] = f2tf32(wv1.x); bs[(lrow+64)*GSTR + lc + 1] = f2tf32(wv1.y);
        bs[(lrow+64)*GSTR + lc + 2] = f2tf32(wv1.z); bs[(lrow+64)*GSTR + lc + 3] = f2tf32(wv1.w);
    }
    __syncthreads();

    const int arow = wm*64 + g;
    const int brow = wn*32 + g;

    int buf = 0;
    for (int k0 = 16; k0 <= NHID; k0 += 16) {
        const bool has = (k0 < NHID);
        if (has) {
            av0 = *(const float4*)(Ag + k0);
            av1 = *(const float4*)(Ag + 64 * NHID + k0);
            wv0 = *(const float4*)(Wg + k0);
            wv1 = *(const float4*)(Wg + 64 * NHID + k0);
        }

        const float* as = As[buf]; const float* bs = Bs[buf];
        #pragma unroll
        for (int ks = 0; ks < 2; ks++) {
            const int kb = ks * 8 + tig;
            float a[4][4];
            #pragma unroll
            for (int i = 0; i < 4; i++) {
                const int r = (arow + i*16) * GSTR;
                a[i][0] = as[r + kb];
                a[i][1] = as[r + 8*GSTR + kb];
                a[i][2] = as[r + kb + 4];
                a[i][3] = as[r + 8*GSTR + kb + 4];
            }
            float b[4][2];
            #pragma unroll
            for (int j = 0; j < 4; j++) {
                const int r = (brow + j*8) * GSTR;
                b[j][0] = bs[r + kb];
                b[j][1] = bs[r + kb + 4];
            }
            #pragma unroll
            for (int i = 0; i < 4; i++)
                #pragma unroll
                for (int j = 0; j < 4; j++)
                    mma_tf32(acc[i][j][0], acc[i][j][1], acc[i][j][2], acc[i][j][3],
                             a[i][0], a[i][1], a[i][2], a[i][3],
                             b[j][0], b[j][1]);
        }

        if (has) {
            float* asn = As[buf^1]; float* bsn = Bs[buf^1];
            asn[lrow*GSTR + lc + 0] = f2tf32(av0.x); asn[lrow*GSTR + lc + 1] = f2tf32(av0.y);
            asn[lrow*GSTR + lc + 2] = f2tf32(av0.z); asn[lrow*GSTR + lc + 3] = f2tf32(av0.w);
            asn[(lrow+64)*GSTR + lc + 0] = f2tf32(av1.x); asn[(lrow+64)*GSTR + lc + 1] = f2tf32(av1.y);
            asn[(lrow+64)*GSTR + lc + 2] = f2tf32(av1.z); asn[(lrow+64)*GSTR + lc + 3] = f2tf32(av1.w);
            bsn[lrow*GSTR + lc + 0] = f2tf32(wv0.x); bsn[lrow*GSTR + lc + 1] = f2tf32(wv0.y);
            bsn[lrow*GSTR + lc + 2] = f2tf32(wv0.z); bsn[lrow*GSTR + lc + 3] = f2tf32(wv0.w);
            bsn[(lrow+64)*GSTR + lc + 0] = f2tf32(wv1.x); bsn[(lrow+64)*GSTR + lc + 1] = f2tf32(wv1.y);
            bsn[(lrow+64)*GSTR + lc + 2] = f2tf32(wv1.z); bsn[(lrow+64)*GSTR + lc + 3] = f2tf32(wv1.w);
        }
        __syncthreads();
        buf ^= 1;
    }

    #pragma unroll
    for (int i = 0; i < 4; i++) {
        #pragma unroll
        for (int j = 0; j < 4; j++) {
            const int row0 = m0 + wm*64 + i*16 + g;
            const int col  = n0 + wn*32 + j*8 + tig*2;
            float2 v0 = make_float2(acc[i][j][0], acc[i][j][1]);
            float2 v1 = make_float2(acc[i][j][2], acc[i][j][3]);
            if (MODE == 0) {
                *(float2*)&C[(size_t)row0 * NHID + col]       = v0;
                *(float2*)&C[(size_t)(row0+8) * NHID + col]   = v1;
            } else {
                const int h = col >> 7, d = col & 127;
                {
                    const int b = row0 >> 11, s = row0 & 2047;
                    *(float2*)&C[(size_t)(b*NH + h) * bh_stride + (size_t)s*ND + d] = v0;
                }
                {
                    const int r1 = row0 + 8;
                    const int b = r1 >> 11, s = r1 & 2047;
                    *(float2*)&C[(size_t)(b*NH + h) * bh_stride + (size_t)s*ND + d] = v1;
                }
            }
        }
    }
}

// ---------------------------------------------------------------------------
// Tensor-core flash attention (causal), tf32 mma, cp.async-pipelined K/V.
// One block per (64-row q-tile, b*h). 256 threads = 8 warps (2 M x 4 N).
// K/V double-buffered raw-fp32 in smem (stride 132), streamed with cp.async
// one tile ahead. V kept row-major [s][d]; PV B-fragments read it directly
// (banks 4*tig+g, conflict-free). tf32 cvt (rna) at fragment-load time for
// K/V; Q and P converted at store time. Softmax exact fp32.
// ---------------------------------------------------------------------------
#define AQS 132
#define AKS 132
#define AVS 132
#define APS 68
#define ATTN_SMEM ((64*AQS + 2*64*AKS + 2*64*AVS + 64*APS + 256 + 256) * 4)  // 188416

__global__ __launch_bounds__(256)
void attn_tc(const float* __restrict__ Q, const float* __restrict__ KV,
             float* __restrict__ ctx)
{
    extern __shared__ float sm[];
    float* Qs   = sm;                    // [64][AQS]
    float* Ksb  = Qs  + 64*AQS;          // [2][64][AKS]
    float* Vsb  = Ksb + 2*64*AKS;        // [2][64][AVS]
    float* Ps   = Vsb + 2*64*AVS;        // [64][APS]
    float* rmax = Ps  + 64*APS;          // [4][64]
    float* rsum = rmax + 256;            // [4][64]

    const int qt = gridDim.x - 1 - blockIdx.x;   // longest blocks first
    const int bh = blockIdx.y;
    const int q0 = qt << 6;
    const int tid  = threadIdx.x;
    const int lane = tid & 31;
    const int wid  = tid >> 5;
    const int wm   = wid & 1;     // 2 warps in M (q rows)
    const int wn   = wid >> 1;    // 4 warps in N
    const int g    = lane >> 4 ? (lane >> 2) : (lane >> 2);  // 0..7 (lane>>2)
    const int gg   = lane >> 2;   // 0..7
    const int tig  = lane & 3;    // 0..3

    const float* Qg = Q  + ((size_t)bh * NS + q0) * ND;
    const float* Kg = KV + (size_t)bh * 2 * NS * ND;
    const float* Vg = Kg + (size_t)NS * ND;

    // ---- cp.async loader mapping: 64 rows x 128 floats; 4 threads/row,
    //      each thread 8 x 16B chunks at cols cu + 16*c
    const int crow = tid >> 2;         // 0..63
    const int cu   = (tid & 3) << 2;   // 0,4,8,12
    const uint32_t kdst0 = smem_u32(Ksb) + (uint32_t)(crow*AKS + cu) * 4;
    const uint32_t vdst0 = smem_u32(Vsb) + (uint32_t)(crow*AVS + cu) * 4;
    const uint32_t bufstride = (uint32_t)(64*AKS) * 4;

#define ISSUE_TILE(kt_, bsel_)                                                   \
    {                                                                            \
        const float* ks = Kg + (size_t)(((kt_) << 6) + crow) * ND + cu;          \
        const float* vs = Vg + (size_t)(((kt_) << 6) + crow) * ND + cu;          \
        const uint32_t kd = kdst0 + (bsel_) * bufstride;                         \
        const uint32_t vd = vdst0 + (bsel_) * bufstride;                         \
        _Pragma("unroll")                                                        \
        for (int c = 0; c < 8; c++) {                                            \
            asm volatile("cp.async.ca.shared.global [%0], [%1], 16;"             \
                :: "r"(kd + c*64u), "l"(ks + c*16) : "memory");                  \
            asm volatile("cp.async.ca.shared.global [%0], [%1], 16;"             \
                :: "r"(vd + c*64u), "l"(vs + c*16) : "memory");                  \
        }                                                                        \
        asm volatile("cp.async.commit_group;" ::: "memory");                     \
    }

    // ---- load Q tile (row-major, tf32 at store)
    {
        const int ldc2  = tid & 1;
        const int ldr   = (tid >> 1) & 63;
        const int ldch0 = tid >> 7;
        #pragma unroll
        for (int it = 0; it < 8; it++) {
            const int d4 = ((it*2 + ldch0) << 1) | ldc2;   // 0..31
            float4 v = *(const float4*)&Qg[(size_t)ldr * ND + (d4 << 2)];
            float4 t = make_float4(f2tf32(v.x), f2tf32(v.y), f2tf32(v.z), f2tf32(v.w));
            *(float4*)&Qs[ldr*AQS + (d4 << 2)] = t;
        }
    }

    // prefetch K/V tile 0
    ISSUE_TILE(0, 0);

    float o_acc[2][4][4];
    #pragma unroll
    for (int i = 0; i < 2; i++)
        #pragma unroll
        for (int j = 0; j < 4; j++)
            #pragma unroll
            for (int r = 0; r < 4; r++) o_acc[i][j][r] = 0.f;
    float m_st[2][2], l_st[2][2];
    #pragma unroll
    for (int i = 0; i < 2; i++)
        #pragma unroll
        for (int h = 0; h < 2; h++) { m_st[i][h] = -1e30f; l_st[i][h] = 0.f; }

    const float scale = 0.08838834764831843f;

    for (int kt = 0; kt <= qt; kt++) {
        const int k0 = kt << 6;
        asm volatile("cp.async.wait_group 0;" ::: "memory");
        __syncthreads();   // tile kt arrived; all reads of buffer (kt-1) done

        if (kt < qt) ISSUE_TILE(kt + 1, (kt + 1) & 1);

        const float* Kc = Ksb + (kt & 1) * 64*AKS;
        const float* Vc = Vsb + (kt & 1) * 64*AVS;

        // ---- S = Q K^T : warp tile 32x16, k=128
        float s_acc[2][2][4];
        #pragma unroll
        for (int i = 0; i < 2; i++)
            #pragma unroll
            for (int j = 0; j < 2; j++)
                #pragma unroll
                for (int r = 0; r < 4; r++) s_acc[i][j][r] = 0.f;

        #pragma unroll
        for (int ks = 0; ks < 16; ks++) {
            const int kb = ks*8 + tig;
            float a[2][4];
            #pragma unroll
            for (int i = 0; i < 2; i++) {
                const int r = (wm*32 + i*16 + gg) * AQS;
                a[i][0] = Qs[r + kb];
                a[i][1] = Qs[r + 8*AQS + kb];
                a[i][2] = Qs[r + kb + 4];
                a[i][3] = Qs[r + 8*AQS + kb + 4];
            }
            float b[2][2];
            #pragma unroll
            for (int j = 0; j < 2; j++) {
                const int r = (wn*16 + j*8 + gg) * AKS;
                b[j][0] = f2tf32(Kc[r + kb]);
                b[j][1] = f2tf32(Kc[r + kb + 4]);
            }
            #pragma unroll
            for (int i = 0; i < 2; i++)
                #pragma unroll
                for (int j = 0; j < 2; j++)
                    mma_tf32(s_acc[i][j][0], s_acc[i][j][1], s_acc[i][j][2], s_acc[i][j][3],
                             a[i][0], a[i][1], a[i][2], a[i][3],
                             b[j][0], b[j][1]);
        }

        // scale + causal mask (diag tile only)
        #pragma unroll
        for (int i = 0; i < 2; i++)
            #pragma unroll
            for (int j = 0; j < 2; j++)
                #pragma unroll
                for (int r = 0; r < 4; r++) s_acc[i][j][r] *= scale;
        if (kt == qt) {
            #pragma unroll
            for (int i = 0; i < 2; i++)
                #pragma unroll
                for (int j = 0; j < 2; j++)
                    #pragma unroll
                    for (int r = 0; r < 4; r++) {
                        const int row = q0 + wm*32 + i*16 + gg + ((r >> 1) << 3);
                        const int col = k0 + wn*16 + j*8 + tig*2 + (r & 1);
                        if (col > row) s_acc[i][j][r] = -1e30f;
                    }
        }

        // ---- phase A: per-warp row max partials
        #pragma unroll
        for (int i = 0; i < 2; i++)
            #pragma unroll
            for (int h = 0; h < 2; h++) {
                float mx = fmaxf(fmaxf(s_acc[i][0][h*2], s_acc[i][0][h*2+1]),
                                 fmaxf(s_acc[i][1][h*2], s_acc[i][1][h*2+1]));
                mx = fmaxf(mx, __shfl_xor_sync(0xffffffffu, mx, 1));
                mx = fmaxf(mx, __shfl_xor_sync(0xffffffffu, mx, 2));
                if (tig == 0) rmax[wn*64 + wm*32 + i*16 + h*8 + gg] = mx;
            }
        __syncthreads();

        // ---- phase B: final max, exp, P -> smem, partial sums, rescale O
        float al[2][2];
        #pragma unroll
        for (int i = 0; i < 2; i++)
            #pragma unroll
            for (int h = 0; h < 2; h++) {
                const int row = wm*32 + i*16 + h*8 + gg;
                float rm = fmaxf(fmaxf(rmax[row], rmax[64+row]),
                                 fmaxf(rmax[128+row], rmax[192+row]));
                const float mnew = fmaxf(m_st[i][h], rm);
                al[i][h] = __expf(m_st[i][h] - mnew);
                m_st[i][h] = mnew;
                float psum = 0.f;
                #pragma unroll
                for (int j = 0; j < 2; j++) {
                    float p0 = f2tf32(__expf(s_acc[i][j][h*2]   - mnew));
                    float p1 = f2tf32(__expf(s_acc[i][j][h*2+1] - mnew));
                    psum += p0 + p1;
                    *(float2*)&Ps[row*APS + wn*16 + j*8 + tig*2] = make_float2(p0, p1);
                }
                psum += __shfl_xor_sync(0xffffffffu, psum, 1);
                psum += __shfl_xor_sync(0xffffffffu, psum, 2);
                if (tig == 0) rsum[wn*64 + row] = psum;
                #pragma unroll
                for (int j = 0; j < 4; j++) {
                    o_acc[i][j][h*2]   *= al[i][h];
                    o_acc[i][j][h*2+1] *= al[i][h];
                }
            }
        __syncthreads();

        // ---- combine row sums
        #pragma unroll
        for (int i = 0; i < 2; i++)
            #pragma unroll
            for (int h = 0; h < 2; h++) {
                const int row = wm*32 + i*16 + h*8 + gg;
                const float tot = (rsum[row] + rsum[64+row]) + (rsum[128+row] + rsum[192+row]);
                l_st[i][h] = l_st[i][h] * al[i][h] + tot;
            }

        // ---- O += P V : warp tile 32x32, k=64; V read row-major [s][d]
        #pragma unroll
        for (int ks = 0; ks < 8; ks++) {
            const int kb = ks*8 + tig;
            float a[2][4];
            #pragma unroll
            for (int i = 0; i < 2; i++) {
                const int r = (wm*32 + i*16 + gg) * APS;
                a[i][0] = Ps[r + kb];
                a[i][1] = Ps[r + 8*APS + kb];
                a[i][2] = Ps[r + kb + 4];
                a[i][3] = Ps[r + 8*APS + kb + 4];
            }
            float b[4][2];
            #pragma unroll
            for (int j = 0; j < 4; j++) {
                const int n = wn*32 + j*8 + gg;
                b[j][0] = f2tf32(Vc[kb*AVS + n]);
                b[j][1] = f2tf32(Vc[(kb+4)*AVS + n]);
            }
            #pragma unroll
            for (int i = 0; i < 2; i++)
                #pragma unroll
                for (int j = 0; j < 4; j++)
                    mma_tf32(o_acc[i][j][0], o_acc[i][j][1], o_acc[i][j][2], o_acc[i][j][3],
                             a[i][0], a[i][1], a[i][2], a[i][3],
                             b[j][0], b[j][1]);
        }
    }

    // ---- epilogue: normalize, write ctx [B,S,H*D]
    const int b = bh >> 4, hh = bh & 15;
    #pragma unroll
    for (int i = 0; i < 2; i++)
        #pragma unroll
        for (int h = 0; h < 2; h++) {
            const int row = wm*32 + i*16 + h*8 + gg;
            const int s = q0 + row;
            const float inv = 1.0f / l_st[i][h];
            float* dst = ctx + (size_t)(b*NS + s) * NHID + hh*ND;
            #pragma unroll
            for (int j = 0; j < 4; j++) {
                const int col = wn*32 + j*8 + tig*2;
                *(float2*)&dst[col] =
                    make_float2(o_acc[i][j][h*2] * inv, o_acc[i][j][h*2+1] * inv);
            }
        }
#undef ISSUE_TILE
}

// ---------------------------------------------------------------------------
// d_out layout: [0, 16777216) = output [B,S,HID]; then kv cache [B,H,2,S,D]
// ---------------------------------------------------------------------------
extern "C" void kernel_launch(void* const* d_in, const int* in_sizes, int n_in,
                              void* d_out, int out_size)
{
    const float* x  = (const float*)d_in[0];
    const float* Wq = (const float*)d_in[1];
    const float* Wk = (const float*)d_in[2];
    const float* Wv = (const float*)d_in[3];
    const float* Wo = (const float*)d_in[4];
    float* out = (float*)d_out;
    float* kv  = out + OUT_ELEMS;

    static float* qp   = nullptr;
    static float* ctxp = nullptr;
    if (!qp) {
        cudaGetSymbolAddress((void**)&qp,   g_q);
        cudaGetSymbolAddress((void**)&ctxp, g_ctx);
        cudaFuncSetAttribute(attn_tc,
                             cudaFuncAttributeMaxDynamicSharedMemorySize, ATTN_SMEM);
    }

    dim3 ggrid(NHID/128, NM/128);   // (16, 64)

    gemm_tf32<1><<<ggrid, 256>>>(x, Wq, qp,                 NS*ND);     // Q -> [B,H,S,D]
    gemm_tf32<1><<<ggrid, 256>>>(x, Wk, kv,                 2*NS*ND);   // K -> cache slot 0
    gemm_tf32<1><<<ggrid, 256>>>(x, Wv, kv + (size_t)NS*ND, 2*NS*ND);   // V -> cache slot 1

    attn_tc<<<dim3(NS/64, NB*NH), 256, ATTN_SMEM>>>(qp, kv, ctxp);

    gemm_tf32<0><<<ggrid, 256>>>(ctxp, Wo, out, 0);
}